// round 1
// baseline (speedup 1.0000x reference)
#include <cuda_runtime.h>
#include <cstdint>

#define N_NODES 50000
#define N_EDGES 1600000
#define D_FEAT  128

// Intermediate buffer for the first propagation round (no cudaMalloc allowed).
__device__ float g_scratch[(size_t)N_NODES * D_FEAT];

// Zero a float buffer with vectorized stores.
__global__ void zero_kernel(float4* __restrict__ p, int n4) {
    int i = blockIdx.x * blockDim.x + threadIdx.x;
    if (i < n4) p[i] = make_float4(0.f, 0.f, 0.f, 0.f);
}

// One warp per edge. Lane l owns floats [4l, 4l+4) of the 128-wide feature row.
// Gather x[col[e]] (float4), scale by vals[e], RED.v4 into out[row[e]].
__global__ void __launch_bounds__(256) spmm_kernel(
    const float* __restrict__ x,
    const int*   __restrict__ adj_row,
    const int*   __restrict__ adj_col,
    const float* __restrict__ adj_vals,
    float*       __restrict__ out,
    int n_edges)
{
    int gwarp = (blockIdx.x * blockDim.x + threadIdx.x) >> 5;
    int lane  = threadIdx.x & 31;
    if (gwarp >= n_edges) return;

    int   r = __ldg(adj_row  + gwarp);
    int   c = __ldg(adj_col  + gwarp);
    float v = __ldg(adj_vals + gwarp);

    const float4* xrow = reinterpret_cast<const float4*>(x + (size_t)c * D_FEAT);
    float4 m = __ldg(xrow + lane);
    m.x *= v; m.y *= v; m.z *= v; m.w *= v;

    float* o = out + (size_t)r * D_FEAT + lane * 4;
    asm volatile("red.global.add.v4.f32 [%0], {%1, %2, %3, %4};"
                 :: "l"(o), "f"(m.x), "f"(m.y), "f"(m.z), "f"(m.w)
                 : "memory");
}

extern "C" void kernel_launch(void* const* d_in, const int* in_sizes, int n_in,
                              void* d_out, int out_size) {
    const float* x        = (const float*)d_in[0];
    const int*   adj_row  = (const int*)  d_in[1];
    const int*   adj_col  = (const int*)  d_in[2];
    const float* adj_vals = (const float*)d_in[3];
    float*       out      = (float*)d_out;

    int n_edges = in_sizes[1];

    float* scratch;
    cudaGetSymbolAddress((void**)&scratch, g_scratch);

    const int n_elems = N_NODES * D_FEAT;
    const int n4 = n_elems / 4;
    const int ZT = 256;
    const int zb = (n4 + ZT - 1) / ZT;

    const int THREADS = 256;
    const int WARPS_PER_BLOCK = THREADS / 32;
    const int sb = (n_edges + WARPS_PER_BLOCK - 1) / WARPS_PER_BLOCK;

    // Round 1: scratch = A @ x
    zero_kernel<<<zb, ZT>>>((float4*)scratch, n4);
    spmm_kernel<<<sb, THREADS>>>(x, adj_row, adj_col, adj_vals, scratch, n_edges);

    // Round 2: out = A @ scratch   (d_out is poisoned; must zero first)
    zero_kernel<<<zb, ZT>>>((float4*)out, n4);
    spmm_kernel<<<sb, THREADS>>>(scratch, adj_row, adj_col, adj_vals, out, n_edges);
}

// round 2
// speedup vs baseline: 1.7684x; 1.7684x over previous
#include <cuda_runtime.h>
#include <cstdint>

#define N_NODES 50000
#define N_EDGES 1600000
#define D_FEAT  128
#define NV4     (D_FEAT / 4)   // 32 float4 per row

// Scratch (no cudaMalloc allowed): intermediate x, CSR arrays.
__device__ float g_scratch[(size_t)N_NODES * D_FEAT];
__device__ int   g_counts [N_NODES];
__device__ int   g_row_ptr[N_NODES + 1];
__device__ int   g_cursor [N_NODES];
__device__ int   g_scol   [N_EDGES];
__device__ float g_sval   [N_EDGES];

// ---------------- CSR build ----------------

__global__ void zero_counts_kernel(int* __restrict__ counts) {
    int i = blockIdx.x * blockDim.x + threadIdx.x;
    if (i < N_NODES) counts[i] = 0;
}

__global__ void hist_kernel(const int* __restrict__ adj_row, int* __restrict__ counts,
                            int n_edges) {
    int e = blockIdx.x * blockDim.x + threadIdx.x;
    if (e < n_edges) atomicAdd(&counts[adj_row[e]], 1);
}

// Single-block exclusive scan over N_NODES counts (warp-shuffle based).
__global__ void __launch_bounds__(1024) scan_kernel(const int* __restrict__ counts,
                                                    int* __restrict__ row_ptr,
                                                    int* __restrict__ cursor) {
    __shared__ int warp_sums[32];
    __shared__ int carry_sh;
    const int tid  = threadIdx.x;
    const int lane = tid & 31;
    const int wid  = tid >> 5;
    if (tid == 0) carry_sh = 0;
    __syncthreads();

    for (int base = 0; base < N_NODES; base += 1024) {
        int i = base + tid;
        int v = (i < N_NODES) ? counts[i] : 0;

        // warp inclusive scan
        int incl = v;
        #pragma unroll
        for (int off = 1; off < 32; off <<= 1) {
            int t = __shfl_up_sync(0xffffffffu, incl, off);
            if (lane >= off) incl += t;
        }
        if (lane == 31) warp_sums[wid] = incl;
        __syncthreads();

        // warp 0 scans the 32 warp sums (exclusive)
        if (wid == 0) {
            int s = warp_sums[lane];
            int si = s;
            #pragma unroll
            for (int off = 1; off < 32; off <<= 1) {
                int t = __shfl_up_sync(0xffffffffu, si, off);
                if (lane >= off) si += t;
            }
            warp_sums[lane] = si - s;   // exclusive
        }
        __syncthreads();

        int carry = carry_sh;
        int excl = incl - v + warp_sums[wid] + carry;
        if (i < N_NODES) { row_ptr[i] = excl; cursor[i] = excl; }
        __syncthreads();
        if (tid == 1023) carry_sh = excl + v;   // new running total
        __syncthreads();
    }
    if (tid == 0) row_ptr[N_NODES] = carry_sh;
}

__global__ void scatter_kernel(const int* __restrict__ adj_row,
                               const int* __restrict__ adj_col,
                               const float* __restrict__ adj_vals,
                               int* __restrict__ cursor,
                               int* __restrict__ scol,
                               float* __restrict__ sval,
                               int n_edges) {
    int e = blockIdx.x * blockDim.x + threadIdx.x;
    if (e >= n_edges) return;
    int r = adj_row[e];
    int p = atomicAdd(&cursor[r], 1);
    scol[p] = adj_col[e];
    sval[p] = adj_vals[e];
}

// ---------------- CSR SpMM: warp per row, register accumulation ----------------

__global__ void __launch_bounds__(256) spmm_csr_kernel(
    const float4* __restrict__ x4,
    const int*    __restrict__ row_ptr,
    const int*    __restrict__ scol,
    const float*  __restrict__ sval,
    float4*       __restrict__ out4)
{
    int row  = (blockIdx.x * blockDim.x + threadIdx.x) >> 5;
    int lane = threadIdx.x & 31;
    if (row >= N_NODES) return;

    int start = row_ptr[row];
    int end   = row_ptr[row + 1];

    float4 acc = make_float4(0.f, 0.f, 0.f, 0.f);

    for (int base = start; base < end; base += 32) {
        int n = end - base;
        if (n > 32) n = 32;
        int   c = 0;
        float v = 0.f;
        if (lane < n) {
            c = scol[base + lane];
            v = sval[base + lane];
        }
        #pragma unroll 4
        for (int j = 0; j < n; j++) {
            int   cj = __shfl_sync(0xffffffffu, c, j);
            float vj = __shfl_sync(0xffffffffu, v, j);
            float4 m = __ldg(x4 + (size_t)cj * NV4 + lane);
            acc.x += vj * m.x;
            acc.y += vj * m.y;
            acc.z += vj * m.z;
            acc.w += vj * m.w;
        }
    }
    out4[(size_t)row * NV4 + lane] = acc;
}

// ---------------- launch ----------------

extern "C" void kernel_launch(void* const* d_in, const int* in_sizes, int n_in,
                              void* d_out, int out_size) {
    const float* x        = (const float*)d_in[0];
    const int*   adj_row  = (const int*)  d_in[1];
    const int*   adj_col  = (const int*)  d_in[2];
    const float* adj_vals = (const float*)d_in[3];
    float*       out      = (float*)d_out;

    int n_edges = in_sizes[1];

    float *scratch; int *counts, *row_ptr, *cursor, *scol; float *sval;
    cudaGetSymbolAddress((void**)&scratch, g_scratch);
    cudaGetSymbolAddress((void**)&counts,  g_counts);
    cudaGetSymbolAddress((void**)&row_ptr, g_row_ptr);
    cudaGetSymbolAddress((void**)&cursor,  g_cursor);
    cudaGetSymbolAddress((void**)&scol,    g_scol);
    cudaGetSymbolAddress((void**)&sval,    g_sval);

    const int T = 256;

    // ---- CSR build (structure fixed per call) ----
    zero_counts_kernel<<<(N_NODES + T - 1) / T, T>>>(counts);
    hist_kernel<<<(n_edges + T - 1) / T, T>>>(adj_row, counts, n_edges);
    scan_kernel<<<1, 1024>>>(counts, row_ptr, cursor);
    scatter_kernel<<<(n_edges + T - 1) / T, T>>>(adj_row, adj_col, adj_vals,
                                                 cursor, scol, sval, n_edges);

    // ---- two propagation rounds, gather formulation ----
    const int WARPS_PER_BLOCK = T / 32;
    const int sb = (N_NODES + WARPS_PER_BLOCK - 1) / WARPS_PER_BLOCK;

    spmm_csr_kernel<<<sb, T>>>((const float4*)x, row_ptr, scol, sval,
                               (float4*)scratch);
    spmm_csr_kernel<<<sb, T>>>((const float4*)scratch, row_ptr, scol, sval,
                               (float4*)out);
}

// round 3
// speedup vs baseline: 2.3338x; 1.3197x over previous
#include <cuda_runtime.h>
#include <cuda_fp16.h>
#include <cstdint>

#define N_NODES 50000
#define N_EDGES 1600000
#define D_FEAT  128
#define NV4     (D_FEAT / 4)   // 32 float4 per fp32 row
#define NH2     (D_FEAT / 4)   // 32 uint2 (4 halfs) per fp16 row

// Scratch (no cudaMalloc allowed).
__device__ uint2 g_xh      [(size_t)N_NODES * NH2];   // fp16 copy of gather operand
__device__ uint2 g_scratchh[(size_t)N_NODES * NH2];   // fp16 round-1 result
__device__ int   g_counts  [N_NODES];
__device__ int   g_row_ptr [N_NODES + 1];
__device__ int   g_eoff    [N_EDGES];
__device__ int2  g_edges   [N_EDGES];                 // packed (col, val-bits)

// ---------------- fp32 -> fp16 conversion (4 feats / thread) ----------------
__global__ void conv_kernel(const float4* __restrict__ in, uint2* __restrict__ out, int n) {
    int i = blockIdx.x * blockDim.x + threadIdx.x;
    if (i >= n) return;
    float4 f = in[i];
    __half2 h0 = __float22half2_rn(make_float2(f.x, f.y));
    __half2 h1 = __float22half2_rn(make_float2(f.z, f.w));
    uint2 o;
    o.x = *reinterpret_cast<unsigned*>(&h0);
    o.y = *reinterpret_cast<unsigned*>(&h1);
    out[i] = o;
}

// ---------------- CSR build ----------------
__global__ void zero_counts_kernel(int* __restrict__ counts) {
    int i = blockIdx.x * blockDim.x + threadIdx.x;
    if (i < N_NODES) counts[i] = 0;
}

// Histogram + record each edge's rank within its row.
__global__ void hist_kernel(const int* __restrict__ adj_row, int* __restrict__ counts,
                            int* __restrict__ eoff, int n_edges) {
    int e = blockIdx.x * blockDim.x + threadIdx.x;
    if (e >= n_edges) return;
    eoff[e] = atomicAdd(&counts[adj_row[e]], 1);
}

// Single-block exclusive scan over N_NODES counts.
__global__ void __launch_bounds__(1024) scan_kernel(const int* __restrict__ counts,
                                                    int* __restrict__ row_ptr) {
    __shared__ int warp_sums[32];
    __shared__ int carry_sh;
    const int tid  = threadIdx.x;
    const int lane = tid & 31;
    const int wid  = tid >> 5;
    if (tid == 0) carry_sh = 0;
    __syncthreads();

    for (int base = 0; base < N_NODES; base += 1024) {
        int i = base + tid;
        int v = (i < N_NODES) ? counts[i] : 0;

        int incl = v;
        #pragma unroll
        for (int off = 1; off < 32; off <<= 1) {
            int t = __shfl_up_sync(0xffffffffu, incl, off);
            if (lane >= off) incl += t;
        }
        if (lane == 31) warp_sums[wid] = incl;
        __syncthreads();

        if (wid == 0) {
            int s = warp_sums[lane];
            int si = s;
            #pragma unroll
            for (int off = 1; off < 32; off <<= 1) {
                int t = __shfl_up_sync(0xffffffffu, si, off);
                if (lane >= off) si += t;
            }
            warp_sums[lane] = si - s;
        }
        __syncthreads();

        int excl = incl - v + warp_sums[wid] + carry_sh;
        if (i < N_NODES) row_ptr[i] = excl;
        __syncthreads();
        if (tid == 1023) carry_sh = excl + v;
        __syncthreads();
    }
    if (tid == 0) row_ptr[N_NODES] = carry_sh;
}

// Place packed (col, val) at row_ptr[row] + rank. One 8B random write/edge.
__global__ void scatter_kernel(const int* __restrict__ adj_row,
                               const int* __restrict__ adj_col,
                               const float* __restrict__ adj_vals,
                               const int* __restrict__ row_ptr,
                               const int* __restrict__ eoff,
                               int2* __restrict__ edges,
                               int n_edges) {
    int e = blockIdx.x * blockDim.x + threadIdx.x;
    if (e >= n_edges) return;
    int r = adj_row[e];
    int p = row_ptr[r] + eoff[e];
    float v = adj_vals[e];
    edges[p] = make_int2(adj_col[e], __float_as_int(v));
}

// ---------------- CSR SpMM: warp/row, fp16 gather, fp32 accumulate ----------
// OUT_HALF=1: store result as fp16 (uint2/lane); else fp32 (float4/lane).
template <int OUT_HALF>
__global__ void __launch_bounds__(256) spmm_csr_h_kernel(
    const uint2* __restrict__ xh,
    const int*   __restrict__ row_ptr,
    const int2*  __restrict__ edges,
    void*        __restrict__ out)
{
    int row  = (blockIdx.x * blockDim.x + threadIdx.x) >> 5;
    int lane = threadIdx.x & 31;
    if (row >= N_NODES) return;

    int start = row_ptr[row];
    int end   = row_ptr[row + 1];

    float4 acc = make_float4(0.f, 0.f, 0.f, 0.f);

    for (int base = start; base < end; base += 32) {
        int n = end - base;
        if (n > 32) n = 32;
        int2 ep = make_int2(0, 0);
        if (lane < n) ep = __ldg(edges + base + lane);

        #pragma unroll 8
        for (int j = 0; j < n; j++) {
            int   cj = __shfl_sync(0xffffffffu, ep.x, j);
            int   vb = __shfl_sync(0xffffffffu, ep.y, j);
            float vj = __int_as_float(vb);
            uint2 m  = __ldg(xh + (size_t)cj * NH2 + lane);
            __half2 h0 = *reinterpret_cast<__half2*>(&m.x);
            __half2 h1 = *reinterpret_cast<__half2*>(&m.y);
            float2 f0 = __half22float2(h0);
            float2 f1 = __half22float2(h1);
            acc.x = fmaf(vj, f0.x, acc.x);
            acc.y = fmaf(vj, f0.y, acc.y);
            acc.z = fmaf(vj, f1.x, acc.z);
            acc.w = fmaf(vj, f1.y, acc.w);
        }
    }

    if (OUT_HALF) {
        __half2 h0 = __float22half2_rn(make_float2(acc.x, acc.y));
        __half2 h1 = __float22half2_rn(make_float2(acc.z, acc.w));
        uint2 o;
        o.x = *reinterpret_cast<unsigned*>(&h0);
        o.y = *reinterpret_cast<unsigned*>(&h1);
        reinterpret_cast<uint2*>(out)[(size_t)row * NH2 + lane] = o;
    } else {
        reinterpret_cast<float4*>(out)[(size_t)row * NV4 + lane] = acc;
    }
}

// ---------------- launch ----------------
extern "C" void kernel_launch(void* const* d_in, const int* in_sizes, int n_in,
                              void* d_out, int out_size) {
    const float* x        = (const float*)d_in[0];
    const int*   adj_row  = (const int*)  d_in[1];
    const int*   adj_col  = (const int*)  d_in[2];
    const float* adj_vals = (const float*)d_in[3];
    float*       out      = (float*)d_out;

    int n_edges = in_sizes[1];

    uint2 *xh, *scratchh; int *counts, *row_ptr, *eoff; int2 *edges;
    cudaGetSymbolAddress((void**)&xh,       g_xh);
    cudaGetSymbolAddress((void**)&scratchh, g_scratchh);
    cudaGetSymbolAddress((void**)&counts,   g_counts);
    cudaGetSymbolAddress((void**)&row_ptr,  g_row_ptr);
    cudaGetSymbolAddress((void**)&eoff,     g_eoff);
    cudaGetSymbolAddress((void**)&edges,    g_edges);

    const int T = 256;

    // CSR build + fp16 conversion of x.
    zero_counts_kernel<<<(N_NODES + T - 1) / T, T>>>(counts);
    hist_kernel<<<(n_edges + T - 1) / T, T>>>(adj_row, counts, eoff, n_edges);
    const int nconv = N_NODES * NH2;
    conv_kernel<<<(nconv + T - 1) / T, T>>>((const float4*)x, xh, nconv);
    scan_kernel<<<1, 1024>>>(counts, row_ptr);
    scatter_kernel<<<(n_edges + T - 1) / T, T>>>(adj_row, adj_col, adj_vals,
                                                 row_ptr, eoff, edges, n_edges);

    // Two propagation rounds.
    const int WPB = T / 32;
    const int sb = (N_NODES + WPB - 1) / WPB;
    spmm_csr_h_kernel<1><<<sb, T>>>(xh, row_ptr, edges, scratchh);
    spmm_csr_h_kernel<0><<<sb, T>>>(scratchh, row_ptr, edges, out);
}